// round 17
// baseline (speedup 1.0000x reference)
#include <cuda_runtime.h>
#include <cuda_bf16.h>
#include <cstdint>

#define NB 4
#define NT 2048
#define NM 256
#define NC 512
#define NH 8
#define ND 64
#define SCALE 0.125f   // 1/sqrt(64)

typedef unsigned short u16;

// ---------------- scratch (device globals; no allocation allowed) ----------------
__device__ float g_bias[NB*NH*NT];
__device__ float g_u1[NB*NT*NC];
__device__ float g_u2[NB*NT*NC];

// split-bf16 scratch
__device__ __align__(16) u16 g_xhi[NB*NT*NC],  g_xlo[NB*NT*NC];
__device__ __align__(16) u16 g_yhi[NB*NM*NC],  g_ylo[NB*NM*NC];
__device__ __align__(16) u16 g_W1hi[3*NC*NC],  g_W1lo[3*NC*NC];
__device__ __align__(16) u16 g_W2hi[3*NC*NC],  g_W2lo[3*NC*NC];
__device__ __align__(16) u16 g_W3hi[NC*NC],    g_W3lo[NC*NC];
__device__ __align__(16) u16 g_W4hi[NC*NC],    g_W4lo[NC*NC];
__device__ __align__(16) u16 g_W5hi[NC*NC],    g_W5lo[NC*NC];
__device__ __align__(16) u16 g_shi[NB*NT*NC],  g_slo[NB*NT*NC];
__device__ __align__(16) u16 g_chi[NB*NT*NC],  g_clo[NB*NT*NC];

// attention operands, bf16 hi/lo, head layout
__device__ __align__(16) u16 g_qxhi[NB*NH*NT*ND],  g_qxlo[NB*NH*NT*ND];
__device__ __align__(16) u16 g_kxhi[NB*NH*NT*ND],  g_kxlo[NB*NH*NT*ND];
__device__ __align__(16) u16 g_vxnhi[NB*NH*NT*ND], g_vxnlo[NB*NH*NT*ND];  // [BH][T][D]
__device__ __align__(16) u16 g_vxthi[NB*NH*NT*ND], g_vxtlo[NB*NH*NT*ND];  // [BH][D][T]
__device__ __align__(16) u16 g_qyhi[NB*NH*NM*ND],  g_qylo[NB*NH*NM*ND];
__device__ __align__(16) u16 g_kyhi[NB*NH*NM*ND],  g_kylo[NB*NH*NM*ND];
__device__ __align__(16) u16 g_vynhi[NB*NH*NM*ND], g_vynlo[NB*NH*NM*ND];  // [BH][M][D]
__device__ __align__(16) u16 g_vythi[NB*NH*NM*ND], g_vytlo[NB*NH*NM*ND];  // [BH][D][M]

// ---------------- helpers ----------------
__device__ __forceinline__ void mma16816(float* c, const unsigned* a, const unsigned* b) {
    asm volatile(
        "mma.sync.aligned.m16n8k16.row.col.f32.bf16.bf16.f32 "
        "{%0,%1,%2,%3}, {%4,%5,%6,%7}, {%8,%9}, {%0,%1,%2,%3};\n"
        : "+f"(c[0]), "+f"(c[1]), "+f"(c[2]), "+f"(c[3])
        : "r"(a[0]), "r"(a[1]), "r"(a[2]), "r"(a[3]), "r"(b[0]), "r"(b[1]));
}

__device__ __forceinline__ void ldsm4(unsigned* r, unsigned addr) {
    asm volatile("ldmatrix.sync.aligned.m8n8.x4.shared.b16 {%0,%1,%2,%3}, [%4];"
        : "=r"(r[0]), "=r"(r[1]), "=r"(r[2]), "=r"(r[3]) : "r"(addr));
}

__device__ __forceinline__ unsigned sptr(const void* p) {
    return (unsigned)__cvta_generic_to_shared(p);
}

__device__ __forceinline__ void split1(float v, __nv_bfloat16& h, __nv_bfloat16& l) {
    h = __float2bfloat16(v);
    l = __float2bfloat16(v - __bfloat162float(h));
}

__device__ __forceinline__ unsigned packu(__nv_bfloat16 a, __nv_bfloat16 b) {
    __nv_bfloat162 t = __halves2bfloat162(a, b);
    return *(unsigned*)&t;
}

__device__ __forceinline__ void split_store2(float a, float b, u16* hip, u16* lop) {
    __nv_bfloat16 h0,h1,l0,l1;
    split1(a,h0,l0); split1(b,h1,l1);
    *(__nv_bfloat162*)hip = __halves2bfloat162(h0,h1);
    *(__nv_bfloat162*)lop = __halves2bfloat162(l0,l1);
}

__device__ __forceinline__ void split_store4(float4 w, u16* hip, u16* lop) {
    split_store2(w.x, w.y, hip, lop);
    split_store2(w.z, w.w, hip + 2, lop + 2);
}

// sum two fp32x8 and split into packed bf16 hi/lo uint4s
__device__ __forceinline__ void fsplit8(float4 a0, float4 a1, float4 b0, float4 b1,
                                        uint4& hv, uint4& lv) {
    float v[8] = {a0.x+b0.x, a0.y+b0.y, a0.z+b0.z, a0.w+b0.w,
                  a1.x+b1.x, a1.y+b1.y, a1.z+b1.z, a1.w+b1.w};
    unsigned h[4], l[4];
    #pragma unroll
    for (int j = 0; j < 4; j++) {
        __nv_bfloat16 h0,l0,h1,l1;
        split1(v[2*j], h0, l0); split1(v[2*j+1], h1, l1);
        h[j] = packu(h0, h1); l[j] = packu(l0, l1);
    }
    hv = make_uint4(h[0], h[1], h[2], h[3]);
    lv = make_uint4(l[0], l[1], l[2], l[3]);
}

// ---------------- merged split-convert: x then y ----------------
__global__ void __launch_bounds__(256) convert_split_all(
    const float4* __restrict__ xin, u16* __restrict__ xhi, u16* __restrict__ xlo, int n4x,
    const float4* __restrict__ yin, u16* __restrict__ yhi, u16* __restrict__ ylo, int n4y)
{
    int i = blockIdx.x * 256 + threadIdx.x;
    if (i < n4x) {
        split_store4(xin[i], xhi + i*4, xlo + i*4);
    } else {
        int j = i - n4x;
        if (j < n4y) split_store4(yin[j], yhi + j*4, ylo + j*4);
    }
}

// ---------------- merged transpose+split for all 5 weights (z selects) ----------------
__global__ void __launch_bounds__(256) transW_all(
    const float* __restrict__ W0, u16* __restrict__ h0p, u16* __restrict__ l0p,
    const float* __restrict__ W1, u16* __restrict__ h1p, u16* __restrict__ l1p,
    const float* __restrict__ W2, u16* __restrict__ h2p, u16* __restrict__ l2p,
    const float* __restrict__ W3, u16* __restrict__ h3p, u16* __restrict__ l3p,
    const float* __restrict__ W4, u16* __restrict__ h4p, u16* __restrict__ l4p)
{
    const int z = blockIdx.z;
    const float* W; u16 *hi, *lo; int N;
    switch (z) {
        case 0: W = W0; hi = h0p; lo = l0p; N = 3*NC; break;
        case 1: W = W1; hi = h1p; lo = l1p; N = 3*NC; break;
        case 2: W = W2; hi = h2p; lo = l2p; N = NC; break;
        case 3: W = W3; hi = h3p; lo = l3p; N = NC; break;
        default: W = W4; hi = h4p; lo = l4p; N = NC; break;
    }
    const int K = NC;
    if ((int)blockIdx.x * 32 >= N) return;

    __shared__ float tile[32][33];
    const int n0 = blockIdx.x * 32, k0 = blockIdx.y * 32;
    const int tx = threadIdx.x, ty = threadIdx.y;
    #pragma unroll
    for (int j = 0; j < 32; j += 8)
        tile[ty + j][tx] = W[(size_t)(k0 + ty + j) * N + n0 + tx];
    __syncthreads();
    #pragma unroll
    for (int j = 0; j < 32; j += 8) {
        __nv_bfloat16 h, l; split1(tile[tx][ty + j], h, l);
        size_t idx = (size_t)(n0 + ty + j) * K + k0 + tx;
        hi[idx] = *(u16*)&h;
        lo[idx] = *(u16*)&l;
    }
}

// ---------------- merged V transpose (x and y): [BH][T][64] -> [BH][64][T] ----------------
__global__ void __launch_bounds__(256) vtrans16_all()
{
    const int bh = blockIdx.z;
    const bool isx = blockIdx.x < (NT/32);
    const int T = isx ? NT : NM;
    const int t0 = (isx ? blockIdx.x : (blockIdx.x - NT/32)) * 32;
    const int d0 = blockIdx.y * 32;
    const u16* in_hi  = isx ? g_vxnhi : g_vynhi;
    const u16* in_lo  = isx ? g_vxnlo : g_vynlo;
    u16* out_hi = isx ? g_vxthi : g_vythi;
    u16* out_lo = isx ? g_vxtlo : g_vytlo;

    __shared__ u16 th[32][34], tl[32][34];
    const int tx = threadIdx.x, ty = threadIdx.y;
    #pragma unroll
    for (int j = 0; j < 32; j += 8) {
        const size_t src = ((size_t)bh * T + t0 + ty + j) * ND + d0 + tx;
        th[ty + j][tx] = in_hi[src];
        tl[ty + j][tx] = in_lo[src];
    }
    __syncthreads();
    #pragma unroll
    for (int j = 0; j < 32; j += 8) {
        const size_t dst = ((size_t)bh * ND + d0 + ty + j) * T + t0 + tx;
        out_hi[dst] = th[tx][ty + j];
        out_lo[dst] = tl[tx][ty + j];
    }
}

// =====================================================================
// split-bf16 tensor-core GEMM; ldmatrix fragment loads.
// EPI 1: out = sigmoid(acc+bias) * (multhi+multlo)     [gates]
// EPI 3: qkv scatter: q/k/v as bf16 hi/lo splits
// EPI 4: A loaded as fp32 (Af1+Af2), split inline; out = acc + bias  [proj]
// =====================================================================
template<int EPI>
__global__ void __launch_bounds__(256) bgemm(
    const __nv_bfloat16* __restrict__ Ahi, const __nv_bfloat16* __restrict__ Alo,
    const __nv_bfloat16* __restrict__ Bhi, const __nv_bfloat16* __restrict__ Blo,
    const float* __restrict__ bias,
    const u16* __restrict__ multhi, const u16* __restrict__ multlo,
    float* __restrict__ out,
    const float* __restrict__ Af1, const float* __restrict__ Af2,
    u16* __restrict__ qbh, u16* __restrict__ qbl,
    u16* __restrict__ kbh, u16* __restrict__ kbl,
    u16* __restrict__ vbh, u16* __restrict__ vbl,
    int N, int K, int Tseq)
{
    __shared__ __align__(16) u16 sA[2][2][128][24];
    __shared__ __align__(16) u16 sB[2][2][128][24];

    const int tid = threadIdx.x;
    const int m0 = blockIdx.y * 128, n0 = blockIdx.x * 128;
    const int warp = tid >> 5, lane = tid & 31;
    const int wm = warp >> 1, wn = warp & 1;
    const int g = lane >> 2, tq2 = (lane & 3) * 2;

    float acc[2][8][4];
    #pragma unroll
    for (int i = 0; i < 2; i++)
        #pragma unroll
        for (int j = 0; j < 8; j++)
            #pragma unroll
            for (int r = 0; r < 4; r++) acc[i][j][r] = 0.f;

    const int lrow = tid >> 1, lhalf = (tid & 1) * 8;
    const __nv_bfloat16* pAhi = Ahi + (size_t)(m0 + lrow) * K + lhalf;
    const __nv_bfloat16* pAlo = Alo + (size_t)(m0 + lrow) * K + lhalf;
    const __nv_bfloat16* pBhi = Bhi + (size_t)(n0 + lrow) * K + lhalf;
    const __nv_bfloat16* pBlo = Blo + (size_t)(n0 + lrow) * K + lhalf;
    const float* pA1 = (EPI == 4) ? (Af1 + (size_t)(m0 + lrow) * K + lhalf) : nullptr;
    const float* pA2 = (EPI == 4) ? (Af2 + (size_t)(m0 + lrow) * K + lhalf) : nullptr;

    uint4 va, vb, vc, vd;
    if (EPI == 4) {
        float4 a0 = *(const float4*)pA1, a1 = *(const float4*)(pA1 + 4);
        float4 b0 = *(const float4*)pA2, b1 = *(const float4*)(pA2 + 4);
        fsplit8(a0, a1, b0, b1, va, vb);
    } else {
        va = *(const uint4*)pAhi;
        vb = *(const uint4*)pAlo;
    }
    vc = *(const uint4*)pBhi;
    vd = *(const uint4*)pBlo;
    *(uint4*)&sA[0][0][lrow][lhalf] = va;
    *(uint4*)&sA[0][1][lrow][lhalf] = vb;
    *(uint4*)&sB[0][0][lrow][lhalf] = vc;
    *(uint4*)&sB[0][1][lrow][lhalf] = vd;
    __syncthreads();

    const int lr7 = lane & 7;
    const int a_radd = ((lane >> 3) & 1) << 3;
    const int a_cadd = ((lane >> 4) << 3);
    const int b_radd = ((lane >> 4) << 3);
    const int b_cadd = (((lane >> 3) & 1) << 3);

    const int nk = K >> 4;
    int buf = 0;
    for (int kt = 0; kt < nk; kt++) {
        if (kt + 1 < nk) {
            int k0 = (kt + 1) << 4;
            if (EPI == 4) {
                float4 a0 = *(const float4*)(pA1 + k0), a1 = *(const float4*)(pA1 + k0 + 4);
                float4 b0 = *(const float4*)(pA2 + k0), b1 = *(const float4*)(pA2 + k0 + 4);
                fsplit8(a0, a1, b0, b1, va, vb);
            } else {
                va = *(const uint4*)(pAhi + k0);
                vb = *(const uint4*)(pAlo + k0);
            }
            vc = *(const uint4*)(pBhi + k0);
            vd = *(const uint4*)(pBlo + k0);
        }
        unsigned ah[2][4], al[2][4];
        #pragma unroll
        for (int mt = 0; mt < 2; mt++) {
            const int ra = wm * 32 + mt * 16 + lr7 + a_radd;
            ldsm4(ah[mt], sptr(&sA[buf][0][ra][a_cadd]));
            ldsm4(al[mt], sptr(&sA[buf][1][ra][a_cadd]));
        }
        #pragma unroll
        for (int np = 0; np < 4; np++) {
            const int rb = wn * 64 + np * 16 + lr7 + b_radd;
            unsigned bh4[4], bl4[4];
            ldsm4(bh4, sptr(&sB[buf][0][rb][b_cadd]));
            ldsm4(bl4, sptr(&sB[buf][1][rb][b_cadd]));
            #pragma unroll
            for (int h = 0; h < 2; h++) {
                #pragma unroll
                for (int mt = 0; mt < 2; mt++) {
                    float* c = acc[mt][np * 2 + h];
                    mma16816(c, ah[mt], &bh4[h * 2]);
                    mma16816(c, ah[mt], &bl4[h * 2]);
                    mma16816(c, al[mt], &bh4[h * 2]);
                }
            }
        }
        if (kt + 1 < nk) {
            int nb = buf ^ 1;
            *(uint4*)&sA[nb][0][lrow][lhalf] = va;
            *(uint4*)&sA[nb][1][lrow][lhalf] = vb;
            *(uint4*)&sB[nb][0][lrow][lhalf] = vc;
            *(uint4*)&sB[nb][1][lrow][lhalf] = vd;
            __syncthreads();
            buf = nb;
        }
    }

    #pragma unroll
    for (int mt = 0; mt < 2; mt++) {
        #pragma unroll
        for (int nt = 0; nt < 8; nt++) {
            const int r0 = m0 + wm * 32 + mt * 16 + g;
            const int col = n0 + wn * 64 + nt * 8 + tq2;
            const float b0 = bias[col], b1 = bias[col + 1];
            float* c = acc[mt][nt];
            #pragma unroll
            for (int rr = 0; rr < 2; rr++) {
                const int r = r0 + rr * 8;
                float v0 = c[rr * 2 + 0] + b0, v1 = c[rr * 2 + 1] + b1;
                if (EPI == 3) {
                    const int which = col >> 9;
                    const int h = (col >> 6) & (NH - 1);
                    const int cc = col & 63;
                    const int b = r / Tseq;
                    const int t = r - b * Tseq;
                    const size_t off = ((size_t)(b * NH + h) * Tseq + t) * ND + cc;
                    u16* hh = (which == 0) ? qbh : (which == 1) ? kbh : vbh;
                    u16* ll = (which == 0) ? qbl : (which == 1) ? kbl : vbl;
                    split_store2(v0, v1, hh + off, ll + off);
                } else if (EPI == 4) {
                    *(float2*)(out + (size_t)r * N + col) = make_float2(v0, v1);
                } else {   // EPI == 1
                    const size_t idx = (size_t)r * N + col;
                    __nv_bfloat162 mh = *(const __nv_bfloat162*)(multhi + idx);
                    __nv_bfloat162 ml = *(const __nv_bfloat162*)(multlo + idx);
                    float mmx = __bfloat162float(mh.x) + __bfloat162float(ml.x);
                    float mmy = __bfloat162float(mh.y) + __bfloat162float(ml.y);
                    float s0 = 1.f / (1.f + __expf(-v0));
                    float s1 = 1.f / (1.f + __expf(-v1));
                    *(float2*)(out + idx) = make_float2(s0 * mmx, s1 * mmy);
                }
            }
        }
    }
}

// =====================================================================
// FUSED flash-attention (self causal + cross) with split-bf16 MMA.
// QK 2-term; PV 3-term. Outputs bf16 hi/lo only.
// =====================================================================
__global__ void __launch_bounds__(256, 2) attn_fused(
    const u16* __restrict__ qhi,
    const u16* __restrict__ skhi, const u16* __restrict__ sklo,
    const u16* __restrict__ svhi, const u16* __restrict__ svlo,
    const u16* __restrict__ ckhi, const u16* __restrict__ cklo,
    const u16* __restrict__ cvhi, const u16* __restrict__ cvlo,
    const float* __restrict__ biasArr,
    u16* __restrict__ southi, u16* __restrict__ soutlo,
    u16* __restrict__ couthi, u16* __restrict__ coutlo)
{
    __shared__ __align__(16) u16 skh[64][72], skl[64][72];
    __shared__ __align__(16) u16 svh[64][72], svl[64][72];
    __shared__ float sb[64];

    const int bh = blockIdx.y;
    const bool causal = blockIdx.x < 16;
    const int tile = causal ? (15 - (int)blockIdx.x) : ((int)blockIdx.x - 16);
    const int Tk = causal ? NT : NM;
    const u16* __restrict__ khi  = causal ? skhi : ckhi;
    const u16* __restrict__ klo  = causal ? sklo : cklo;
    const u16* __restrict__ vthi = causal ? svhi : cvhi;
    const u16* __restrict__ vtlo = causal ? svlo : cvlo;
    u16* __restrict__ outhi = causal ? southi : couthi;
    u16* __restrict__ outlo = causal ? soutlo : coutlo;

    const int t0 = tile * 128;
    const int tid = threadIdx.x;
    const int warp = tid >> 5, lane = tid & 31;
    const int g = lane >> 2, tq2 = (lane & 3) * 2;
    const int qr0 = t0 + warp * 16;
    const int lr7 = lane & 7;
    const int b_cadd = (lane >> 3) * 8;

    unsigned qa_h[4][4];
    {
        const size_t rA = ((size_t)bh * NT + qr0 + g) * ND;
        const size_t rB = rA + 8 * ND;
        #pragma unroll
        for (int kt = 0; kt < 4; kt++) {
            const int c0 = kt * 16 + tq2, c8 = c0 + 8;
            qa_h[kt][0] = *(const unsigned*)(qhi + rA + c0);
            qa_h[kt][1] = *(const unsigned*)(qhi + rB + c0);
            qa_h[kt][2] = *(const unsigned*)(qhi + rA + c8);
            qa_h[kt][3] = *(const unsigned*)(qhi + rB + c8);
        }
    }

    float accO[8][4];
    #pragma unroll
    for (int i = 0; i < 8; i++)
        #pragma unroll
        for (int j = 0; j < 4; j++) accO[i][j] = 0.f;
    float denA = 0.f, denB = 0.f;

    const int s_end = causal ? (t0 + 128) : NM;
    for (int s0 = 0; s0 < s_end; s0 += 64) {
        #pragma unroll
        for (int i = 0; i < 2; i++) {
            const int idx = tid + i * 256;
            const int row = idx >> 3, c8 = (idx & 7) * 8;
            const size_t kb = ((size_t)bh * Tk + s0 + row) * ND + c8;
            *(uint4*)&skh[row][c8] = *(const uint4*)(khi + kb);
            *(uint4*)&skl[row][c8] = *(const uint4*)(klo + kb);
            const size_t vbs = ((size_t)bh * ND + row) * Tk + s0 + c8;
            *(uint4*)&svh[row][c8] = *(const uint4*)(vthi + vbs);
            *(uint4*)&svl[row][c8] = *(const uint4*)(vtlo + vbs);
        }
        if (causal && tid < 64) sb[tid] = biasArr[(size_t)bh * NT + s0 + tid];
        __syncthreads();

        if (!causal || qr0 + 15 >= s0) {
            unsigned pa_h[4][4], pa_l[4][4];
            #pragma unroll
            for (int nt = 0; nt < 8; nt++) {
                unsigned bh8[8], bl8[8];
                ldsm4(&bh8[0], sptr(&skh[nt*8 + lr7][b_cadd]));
                ldsm4(&bh8[4], sptr(&skh[nt*8 + lr7][32 + b_cadd]));
                ldsm4(&bl8[0], sptr(&skl[nt*8 + lr7][b_cadd]));
                ldsm4(&bl8[4], sptr(&skl[nt*8 + lr7][32 + b_cadd]));
                float c4[4] = {0.f, 0.f, 0.f, 0.f};
                #pragma unroll
                for (int kt = 0; kt < 4; kt++) {
                    mma16816(c4, qa_h[kt], &bh8[kt*2]);
                    mma16816(c4, qa_h[kt], &bl8[kt*2]);
                }
                float b0 = 0.f, b1 = 0.f;
                if (causal) { b0 = sb[nt*8 + tq2]; b1 = sb[nt*8 + tq2 + 1]; }
                float e0 = __expf(c4[0] * SCALE + b0);
                float e1 = __expf(c4[1] * SCALE + b1);
                float e2 = __expf(c4[2] * SCALE + b0);
                float e3 = __expf(c4[3] * SCALE + b1);
                if (causal) {
                    const int key0 = s0 + nt*8 + tq2;
                    const int rA = qr0 + g, rB = rA + 8;
                    if (key0     > rA) e0 = 0.f;
                    if (key0 + 1 > rA) e1 = 0.f;
                    if (key0     > rB) e2 = 0.f;
                    if (key0 + 1 > rB) e3 = 0.f;
                }
                denA += e0 + e1;
                denB += e2 + e3;
                __nv_bfloat16 h0,l0,h1,l1,h2,l2,h3,l3;
                split1(e0,h0,l0); split1(e1,h1,l1); split1(e2,h2,l2); split1(e3,h3,l3);
                const int pk = nt >> 1, sub = (nt & 1) * 2;
                pa_h[pk][sub]     = packu(h0, h1);
                pa_h[pk][sub + 1] = packu(h2, h3);
                pa_l[pk][sub]     = packu(l0, l1);
                pa_l[pk][sub + 1] = packu(l2, l3);
            }
            #pragma unroll
            for (int nt = 0; nt < 8; nt++) {
                unsigned bh8[8], bl8[8];
                ldsm4(&bh8[0], sptr(&svh[nt*8 + lr7][b_cadd]));
                ldsm4(&bh8[4], sptr(&svh[nt*8 + lr7][32 + b_cadd]));
                ldsm4(&bl8[0], sptr(&svl[nt*8 + lr7][b_cadd]));
                ldsm4(&bl8[4], sptr(&svl[nt*8 + lr7][32 + b_cadd]));
                #pragma unroll
                for (int pk = 0; pk < 4; pk++) {
                    mma16816(accO[nt], pa_h[pk], &bh8[pk*2]);
                    mma16816(accO[nt], pa_h[pk], &bl8[pk*2]);
                    mma16816(accO[nt], pa_l[pk], &bh8[pk*2]);
                }
            }
        }
        __syncthreads();
    }

    denA += __shfl_xor_sync(0xffffffffu, denA, 1);
    denA += __shfl_xor_sync(0xffffffffu, denA, 2);
    denB += __shfl_xor_sync(0xffffffffu, denB, 1);
    denB += __shfl_xor_sync(0xffffffffu, denB, 2);
    const float invA = 1.f / denA, invB = 1.f / denB;

    const int b = bh >> 3, h = bh & 7;
    const size_t baseA = ((size_t)(b * NT + qr0 + g)) * NC + h * ND;
    const size_t baseB = ((size_t)(b * NT + qr0 + g + 8)) * NC + h * ND;
    #pragma unroll
    for (int nt = 0; nt < 8; nt++) {
        const int d = nt * 8 + tq2;
        split_store2(accO[nt][0] * invA, accO[nt][1] * invA,
                     outhi + baseA + d, outlo + baseA + d);
        split_store2(accO[nt][2] * invB, accO[nt][3] * invB,
                     outhi + baseB + d, outlo + baseB + d);
    }
}

// =====================================================================
// bias term via MMA; QK 2-term split.
// =====================================================================
__global__ void __launch_bounds__(256, 2) bias_mma()
{
    __shared__ __align__(16) u16 sqh[64][72], sql[64][72];

    const int bh = blockIdx.y;
    const int t0 = blockIdx.x * 128;
    const int tid = threadIdx.x;
    const int warp = tid >> 5, lane = tid & 31;
    const int g = lane >> 2, tq2 = (lane & 3) * 2;
    const int qr0 = t0 + warp * 16;
    const int lr7 = lane & 7;
    const int b_cadd = (lane >> 3) * 8;

    unsigned ka_h[4][4];
    {
        const size_t rA = ((size_t)bh * NT + qr0 + g) * ND;
        const size_t rB = rA + 8 * ND;
        #pragma unroll
        for (int kt = 0; kt < 4; kt++) {
            const int c0 = kt * 16 + tq2, c8 = c0 + 8;
            ka_h[kt][0] = *(const unsigned*)(g_kxhi + rA + c0);
            ka_h[kt][1] = *(const unsigned*)(g_kxhi + rB + c0);
            ka_h[kt][2] = *(const unsigned*)(g_kxhi + rA + c8);
            ka_h[kt][3] = *(const unsigned*)(g_kxhi + rB + c8);
        }
    }

    float denA = 0.f, denB = 0.f, numA = 0.f, numB = 0.f;

    for (int m0 = 0; m0 < NM; m0 += 64) {
        #pragma unroll
        for (int i = 0; i < 2; i++) {
            const int idx = tid + i * 256;
            const int row = idx >> 3, c8 = (idx & 7) * 8;
            const size_t qb = ((size_t)bh * NM + m0 + row) * ND + c8;
            *(uint4*)&sqh[row][c8] = *(const uint4*)(g_qyhi + qb);
            *(uint4*)&sql[row][c8] = *(const uint4*)(g_qylo + qb);
        }
        __syncthreads();

        #pragma unroll
        for (int nt = 0; nt < 8; nt++) {
            unsigned bh8[8], bl8[8];
            ldsm4(&bh8[0], sptr(&sqh[nt*8 + lr7][b_cadd]));
            ldsm4(&bh8[4], sptr(&sqh[nt*8 + lr7][32 + b_cadd]));
            ldsm4(&bl8[0], sptr(&sql[nt*8 + lr7][b_cadd]));
            ldsm4(&bl8[4], sptr(&sql[nt*8 + lr7][32 + b_cadd]));
            float c4[4] = {0.f, 0.f, 0.f, 0.f};
            #pragma unroll
            for (int kt = 0; kt < 4; kt++) {
                mma16816(c4, ka_h[kt], &bh8[kt*2]);
                mma16816(c4, ka_h[kt], &bl8[kt*2]);
            }
            float s0 = c4[0] * SCALE, s1 = c4[1] * SCALE;
            float s2 = c4[2] * SCALE, s3 = c4[3] * SCALE;
            float e0 = __expf(s0), e1 = __expf(s1);
            float e2 = __expf(s2), e3 = __expf(s3);
            denA += e0 + e1;            denB += e2 + e3;
            numA += e0 * s0 + e1 * s1;  numB += e2 * s2 + e3 * s3;
        }
        __syncthreads();
    }

    denA += __shfl_xor_sync(0xffffffffu, denA, 1);
    denA += __shfl_xor_sync(0xffffffffu, denA, 2);
    numA += __shfl_xor_sync(0xffffffffu, numA, 1);
    numA += __shfl_xor_sync(0xffffffffu, numA, 2);
    denB += __shfl_xor_sync(0xffffffffu, denB, 1);
    denB += __shfl_xor_sync(0xffffffffu, denB, 2);
    numB += __shfl_xor_sync(0xffffffffu, numB, 1);
    numB += __shfl_xor_sync(0xffffffffu, numB, 2);

    if ((lane & 3) == 0) {
        g_bias[(size_t)bh * NT + qr0 + g]     = numA / (denA * (float)NM);
        g_bias[(size_t)bh * NT + qr0 + g + 8] = numB / (denB * (float)NM);
    }
}

// ---------------- host launcher ----------------
extern "C" void kernel_launch(void* const* d_in, const int* in_sizes, int n_in,
                              void* d_out, int out_size)
{
    const float* x      = (const float*)d_in[0];
    const float* y      = (const float*)d_in[1];
    // d_in[2]: attn_x_mask (causal tril) — structure known, ignored
    const float* Wqkv_x = (const float*)d_in[3];
    const float* bqkv_x = (const float*)d_in[4];
    const float* Wqkv_y = (const float*)d_in[5];
    const float* bqkv_y = (const float*)d_in[6];
    const float* Wgs    = (const float*)d_in[7];
    const float* bgs    = (const float*)d_in[8];
    const float* Wgc    = (const float*)d_in[9];
    const float* bgc    = (const float*)d_in[10];
    const float* Wp     = (const float*)d_in[11];
    const float* bp     = (const float*)d_in[12];
    float* out = (float*)d_out;

    float *u1, *u2;
    cudaGetSymbolAddress((void**)&u1, g_u1);
    cudaGetSymbolAddress((void**)&u2, g_u2);

    u16 *xhi,*xlo,*yhi,*ylo,*w1hi,*w1lo,*w2hi,*w2lo,*w3hi,*w3lo,*w4hi,*w4lo,*w5hi,*w5lo;
    u16 *shi,*slo,*chi,*clo;
    u16 *qxhi,*qxlo,*kxhi,*kxlo,*vxnhi,*vxnlo,*vxthi,*vxtlo;
    u16 *qyhi,*qylo,*kyhi,*kylo,*vynhi,*vynlo,*vythi,*vytlo;
    cudaGetSymbolAddress((void**)&xhi, g_xhi);   cudaGetSymbolAddress((void**)&xlo, g_xlo);
    cudaGetSymbolAddress((void**)&yhi, g_yhi);   cudaGetSymbolAddress((void**)&ylo, g_ylo);
    cudaGetSymbolAddress((void**)&w1hi, g_W1hi); cudaGetSymbolAddress((void**)&w1lo, g_W1lo);
    cudaGetSymbolAddress((void**)&w2hi, g_W2hi); cudaGetSymbolAddress((void**)&w2lo, g_W2lo);
    cudaGetSymbolAddress((void**)&w3hi, g_W3hi); cudaGetSymbolAddress((void**)&w3lo, g_W3lo);
    cudaGetSymbolAddress((void**)&w4hi, g_W4hi); cudaGetSymbolAddress((void**)&w4lo, g_W4lo);
    cudaGetSymbolAddress((void**)&w5hi, g_W5hi); cudaGetSymbolAddress((void**)&w5lo, g_W5lo);
    cudaGetSymbolAddress((void**)&shi, g_shi);   cudaGetSymbolAddress((void**)&slo, g_slo);
    cudaGetSymbolAddress((void**)&chi, g_chi);   cudaGetSymbolAddress((void**)&clo, g_clo);
    cudaGetSymbolAddress((void**)&qxhi, g_qxhi); cudaGetSymbolAddress((void**)&qxlo, g_qxlo);
    cudaGetSymbolAddress((void**)&kxhi, g_kxhi); cudaGetSymbolAddress((void**)&kxlo, g_kxlo);
    cudaGetSymbolAddress((void**)&vxnhi, g_vxnhi); cudaGetSymbolAddress((void**)&vxnlo, g_vxnlo);
    cudaGetSymbolAddress((void**)&vxthi, g_vxthi); cudaGetSymbolAddress((void**)&vxtlo, g_vxtlo);
    cudaGetSymbolAddress((void**)&qyhi, g_qyhi); cudaGetSymbolAddress((void**)&qylo, g_qylo);
    cudaGetSymbolAddress((void**)&kyhi, g_kyhi); cudaGetSymbolAddress((void**)&kylo, g_kylo);
    cudaGetSymbolAddress((void**)&vynhi, g_vynhi); cudaGetSymbolAddress((void**)&vynlo, g_vynlo);
    cudaGetSymbolAddress((void**)&vythi, g_vythi); cudaGetSymbolAddress((void**)&vytlo, g_vytlo);

    // 0) merged split-convert (x + y) and merged weight transposes
    const int n4x = (NB*NT*NC)/4, n4y = (NB*NM*NC)/4;
    convert_split_all<<<(n4x + n4y + 255)/256, 256>>>(
        (const float4*)x, xhi, xlo, n4x, (const float4*)y, yhi, ylo, n4y);
    transW_all<<<dim3(3*NC/32, NC/32, 5), dim3(32,8)>>>(
        Wqkv_x, w1hi, w1lo, Wqkv_y, w2hi, w2lo,
        Wgs, w3hi, w3lo, Wgc, w4hi, w4lo, Wp, w5hi, w5lo);

    // 1) QKV projections (tensor core; q/k/v all bf16 hi/lo)
    bgemm<3><<<dim3(12, (NB*NT)/128), 256>>>(
        (const __nv_bfloat16*)xhi, (const __nv_bfloat16*)xlo,
        (const __nv_bfloat16*)w1hi, (const __nv_bfloat16*)w1lo,
        bqkv_x, nullptr, nullptr, nullptr, nullptr, nullptr,
        qxhi, qxlo, kxhi, kxlo, vxnhi, vxnlo, 3*NC, NC, NT);
    bgemm<3><<<dim3(12, (NB*NM)/128), 256>>>(
        (const __nv_bfloat16*)yhi, (const __nv_bfloat16*)ylo,
        (const __nv_bfloat16*)w2hi, (const __nv_bfloat16*)w2lo,
        bqkv_y, nullptr, nullptr, nullptr, nullptr, nullptr,
        qyhi, qylo, kyhi, kylo, vynhi, vynlo, 3*NC, NC, NM);

    // 1b) merged V transposes
    vtrans16_all<<<dim3(NT/32 + NM/32, ND/32, NB*NH), dim3(32,8)>>>();

    // 2) cross-softmax bias over keys (tensor core)
    bias_mma<<<dim3(NT/128, NB*NH), 256>>>();

    // 3) FUSED attentions (self causal tiles first, cross fills the tail)
    attn_fused<<<dim3(32, NB*NH), 256>>>(
        qxhi,
        kxhi, kxlo, vxthi, vxtlo,
        kyhi, kylo, vythi, vytlo,
        g_bias,
        shi, slo,
        chi, clo);

    // 4) gates (independent partials): u1 = sig(s@W3+bgs)*c ; u2 = sig(c@W4+bgc)*s
    bgemm<1><<<dim3(4, (NB*NT)/128), 256>>>(
        (const __nv_bfloat16*)shi, (const __nv_bfloat16*)slo,
        (const __nv_bfloat16*)w3hi, (const __nv_bfloat16*)w3lo,
        bgs, chi, clo, u1, nullptr, nullptr,
        nullptr, nullptr, nullptr, nullptr, nullptr, nullptr, NC, NC, 0);
    bgemm<1><<<dim3(4, (NB*NT)/128), 256>>>(
        (const __nv_bfloat16*)chi, (const __nv_bfloat16*)clo,
        (const __nv_bfloat16*)w4hi, (const __nv_bfloat16*)w4lo,
        bgc, shi, slo, u2, nullptr, nullptr,
        nullptr, nullptr, nullptr, nullptr, nullptr, nullptr, NC, NC, 0);

    // 5) output projection: A = (u1 + u2) split inline
    bgemm<4><<<dim3(4, (NB*NT)/128), 256>>>(
        nullptr, nullptr,
        (const __nv_bfloat16*)w5hi, (const __nv_bfloat16*)w5lo,
        bp, nullptr, nullptr, out, u1, u2,
        nullptr, nullptr, nullptr, nullptr, nullptr, nullptr, NC, NC, 0);
}